// round 3
// baseline (speedup 1.0000x reference)
#include <cuda_runtime.h>
#include <cuda_fp16.h>
#include <cstdint>

#define FULLMASK 0xFFFFFFFFu

namespace {
constexpr int   B       = 16;
constexpr int   NQ      = 8;
constexpr int   NS      = 16384;
constexpr int   D       = 128;
constexpr int   H       = 512;
constexpr int   ITERS   = 3;
constexpr float LN_EPS  = 1e-5f;
constexpr float EPS_A   = 1e-8f;
constexpr float SCALE   = 0.088388347648318447f;   // 128^-0.5
constexpr int   CHUNKS  = 64;                      // NS chunks per batch
constexpr int   RPC     = NS / CHUNKS;             // 256 rows per block
constexpr int   D2      = D / 2;                   // half2 elements per row
}

// ---- scratch (static __device__ arrays: allocation-free) ----
__device__ __half2 g_xn[(size_t)B * NS * D2];  // LayerNorm'd inputs, fp16, 67 MB
__device__ float g_slots[B * NQ * D];
__device__ float g_qk[B * NQ * D];             // SCALE * (q @ Wk)
__device__ float g_tt[B * NQ];                 // SCALE * (q . bk)
__device__ float g_U[B * NQ * D];              // sum_j a_ij * xn_j
__device__ float g_den[B * NQ];                // sum_j a_ij

// ============================================================
// Kernel 1: xn = fp16(LayerNorm(inputs)) — one warp per row
// ============================================================
__global__ void ln_in_kernel(const float* __restrict__ inp,
                             const float* __restrict__ w,
                             const float* __restrict__ b) {
    int warp = threadIdx.x >> 5, lane = threadIdx.x & 31;
    size_t row = (size_t)blockIdx.x * 8 + warp;
    const float4 x = *(const float4*)(inp + row * D + lane * 4);
    float s = x.x + x.y + x.z + x.w;
#pragma unroll
    for (int m = 16; m; m >>= 1) s += __shfl_xor_sync(FULLMASK, s, m);
    float mean = s * (1.0f / D);
    float dx = x.x - mean, dy = x.y - mean, dz = x.z - mean, dw = x.w - mean;
    float ss = dx * dx + dy * dy + dz * dz + dw * dw;
#pragma unroll
    for (int m = 16; m; m >>= 1) ss += __shfl_xor_sync(FULLMASK, ss, m);
    float rstd = rsqrtf(ss * (1.0f / D) + LN_EPS);
    const float4 wv = *(const float4*)(w + lane * 4);
    const float4 bv = *(const float4*)(b + lane * 4);
    float ox = dx * rstd * wv.x + bv.x;
    float oy = dy * rstd * wv.y + bv.y;
    float oz = dz * rstd * wv.z + bv.z;
    float ow = dw * rstd * wv.w + bv.w;
    __half2 h0 = __floats2half2_rn(ox, oy);
    __half2 h1 = __floats2half2_rn(oz, ow);
    uint2 packed;
    packed.x = *reinterpret_cast<uint32_t*>(&h0);
    packed.y = *reinterpret_cast<uint32_t*>(&h1);
    *(uint2*)(g_xn + row * D2 + lane * 2) = packed;
}

__global__ void init_slots_kernel(const float* __restrict__ q) {
    int i = blockIdx.x * blockDim.x + threadIdx.x;
    g_slots[i] = q[i];
}

// 128-thread block sum
__device__ __forceinline__ float blockSum4(float v, float* red) {
    int lane = threadIdx.x & 31, w = threadIdx.x >> 5;
#pragma unroll
    for (int m = 16; m; m >>= 1) v += __shfl_xor_sync(FULLMASK, v, m);
    __syncthreads();                 // protect red from prior use
    if (lane == 0) red[w] = v;
    __syncthreads();
    return red[0] + red[1] + red[2] + red[3];
}

// ============================================================
// Kernel 2 (per iter): q = LN(slots)@Wq^T+bq ; qk = SCALE*(q@Wk)
// t = SCALE*(q.bk) ; zero U/den.  One block per (b,i) row.
// ============================================================
__global__ void pre_kernel(const float* __restrict__ wq, const float* __restrict__ bq,
                           const float* __restrict__ wk, const float* __restrict__ bk,
                           const float* __restrict__ lnw, const float* __restrict__ lnb) {
    int row = blockIdx.x;            // b*NQ + i
    int t = threadIdx.x;             // 0..127
    __shared__ float sh[D], sq[D], red[4];
    float s = g_slots[row * D + t];
    float mean = blockSum4(s, red) * (1.0f / D);
    float d0 = s - mean;
    float var = blockSum4(d0 * d0, red) * (1.0f / D);
    float rstd = rsqrtf(var + LN_EPS);
    sh[t] = d0 * rstd * lnw[t] + lnb[t];
    __syncthreads();
    float acc = bq[t];
#pragma unroll 8
    for (int e = 0; e < D; e++) acc = fmaf(sh[e], wq[t * D + e], acc);
    sq[t] = acc;
    __syncthreads();
    float qk = 0.f;
#pragma unroll 8
    for (int d = 0; d < D; d++) qk = fmaf(sq[d], wk[d * D + t], qk);
    g_qk[row * D + t] = qk * SCALE;
    float tb = blockSum4(sq[t] * bk[t], red);
    if (t == 0) { g_tt[row] = tb * SCALE; g_den[row] = 0.f; }
    g_U[row * D + t] = 0.f;
}

// ============================================================
// Kernel 3 (per iter): fused attention streaming pass over xn.
// Per sample j: dots_i = qk_i . xn_j + t_i ; a = softmax_i + EPS;
// accumulate U_i += a_i * xn_j, den_i += a_i.
// Warp per row-group; value-halving cross-lane dot reduction.
// fp16 xn (8B/lane/row); fp32 math; prefetch row r+1.
// ============================================================
__global__ void __launch_bounds__(256, 2) attn_kernel() {
    int b = blockIdx.y;
    int cx = blockIdx.x;
    int tid = threadIdx.x;
    int warp = tid >> 5, lane = tid & 31;
    __shared__ __align__(16) float sqk[NQ * D];
    __shared__ float sUsh[NQ * D];
    __shared__ float st[NQ];
    __shared__ float sden[NQ];
    for (int i = tid; i < NQ * D; i += 256) {
        sqk[i] = g_qk[b * NQ * D + i];
        sUsh[i] = 0.f;
    }
    if (tid < NQ) { st[tid] = g_tt[b * NQ + tid]; sden[tid] = 0.f; }
    __syncthreads();

    float4 rq[NQ];
#pragma unroll
    for (int i = 0; i < NQ; i++) rq[i] = *(const float4*)(sqk + i * D + lane * 4);
    float tb = st[lane >> 2];        // this lane's query role rid = lane>>2

    float U[NQ][4];
#pragma unroll
    for (int i = 0; i < NQ; i++) { U[i][0] = 0.f; U[i][1] = 0.f; U[i][2] = 0.f; U[i][3] = 0.f; }
    float dacc = 0.f;

    const __half2* __restrict__ base =
        g_xn + ((size_t)b * NS + (size_t)cx * RPC + warp * 32) * D2 + lane * 2;

    uint2 raw = *(const uint2*)(base);           // prefetch row 0
#pragma unroll 4
    for (int r = 0; r < 32; r++) {
        uint2 rawc = raw;
        if (r < 31) raw = *(const uint2*)(base + (size_t)(r + 1) * D2);  // prefetch next
        __half2 h0 = *reinterpret_cast<__half2*>(&rawc.x);
        __half2 h1 = *reinterpret_cast<__half2*>(&rawc.y);
        float2 f0 = __half22float2(h0);
        float2 f1 = __half22float2(h1);
        float4 xc; xc.x = f0.x; xc.y = f0.y; xc.z = f1.x; xc.w = f1.y;

        float p[NQ];
#pragma unroll
        for (int i = 0; i < NQ; i++)
            p[i] = fmaf(rq[i].x, xc.x, fmaf(rq[i].y, xc.y, fmaf(rq[i].z, xc.z, rq[i].w * xc.w)));

        // --- value-halving reduction: 8 dots over 32 lanes ---
        float sm0[8];
#pragma unroll
        for (int i = 0; i < 8; i++) sm0[i] = p[i] + __shfl_xor_sync(FULLMASK, p[i], 16);
        bool h16 = (lane & 16) != 0;
        float q0 = h16 ? sm0[4] : sm0[0];
        float q1 = h16 ? sm0[5] : sm0[1];
        float q2 = h16 ? sm0[6] : sm0[2];
        float q3 = h16 ? sm0[7] : sm0[3];
        float t0 = q0 + __shfl_xor_sync(FULLMASK, q0, 8);
        float t1 = q1 + __shfl_xor_sync(FULLMASK, q1, 8);
        float t2 = q2 + __shfl_xor_sync(FULLMASK, q2, 8);
        float t3 = q3 + __shfl_xor_sync(FULLMASK, q3, 8);
        bool h8 = (lane & 8) != 0;
        float u0 = h8 ? t2 : t0;
        float u1 = h8 ? t3 : t1;
        float v0 = u0 + __shfl_xor_sync(FULLMASK, u0, 4);
        float v1 = u1 + __shfl_xor_sync(FULLMASK, u1, 4);
        float w0 = ((lane & 4) != 0) ? v1 : v0;
        w0 += __shfl_xor_sync(FULLMASK, w0, 2);
        w0 += __shfl_xor_sync(FULLMASK, w0, 1);
        // lane now holds full dot for query rid = lane>>2 (x4 redundancy)

        float e = __expf(w0 + tb);
        float ssum = e;
        ssum += __shfl_xor_sync(FULLMASK, ssum, 4);
        ssum += __shfl_xor_sync(FULLMASK, ssum, 8);
        ssum += __shfl_xor_sync(FULLMASK, ssum, 16);   // sum over the 8 roles
        float a_self = __fdividef(e, ssum) + EPS_A;
        dacc += a_self;
        float a[NQ];
#pragma unroll
        for (int i = 0; i < NQ; i++) a[i] = __shfl_sync(FULLMASK, a_self, i * 4);
#pragma unroll
        for (int i = 0; i < NQ; i++) {
            U[i][0] = fmaf(a[i], xc.x, U[i][0]);
            U[i][1] = fmaf(a[i], xc.y, U[i][1]);
            U[i][2] = fmaf(a[i], xc.z, U[i][2]);
            U[i][3] = fmaf(a[i], xc.w, U[i][3]);
        }
    }

    // block-level reduce via shared atomics, then one global pass
#pragma unroll
    for (int i = 0; i < NQ; i++) {
        atomicAdd(&sUsh[i * D + lane * 4 + 0], U[i][0]);
        atomicAdd(&sUsh[i * D + lane * 4 + 1], U[i][1]);
        atomicAdd(&sUsh[i * D + lane * 4 + 2], U[i][2]);
        atomicAdd(&sUsh[i * D + lane * 4 + 3], U[i][3]);
    }
    if ((lane & 3) == 0) atomicAdd(&sden[lane >> 2], dacc);
    __syncthreads();
    for (int i = tid; i < NQ * D; i += 256) atomicAdd(&g_U[b * NQ * D + i], sUsh[i]);
    if (tid < NQ) atomicAdd(&g_den[b * NQ + tid], sden[tid]);
}

// ============================================================
// Kernel 4 (per iter): updates = (U/den)@Wv^T+bv ; GRU ; slots+FF
// One block (128 threads) per (b,i) row.
// ============================================================
__global__ void post_kernel(const float* __restrict__ wv, const float* __restrict__ bv,
                            const float* __restrict__ gwi, const float* __restrict__ gwh,
                            const float* __restrict__ gbi, const float* __restrict__ gbh,
                            const float* __restrict__ w1, const float* __restrict__ b1,
                            const float* __restrict__ w2, const float* __restrict__ b2,
                            const float* __restrict__ lnw, const float* __restrict__ lnb,
                            float* __restrict__ out, int write_out) {
    int row = blockIdx.x;
    int t = threadIdx.x;
    __shared__ float sU[D], sUpd[D], sS[D], sM[H], red[4];
    float den = g_den[row];
    sU[t] = g_U[row * D + t] / den;
    float slot = g_slots[row * D + t];
    sS[t] = slot;
    __syncthreads();
    float upd = bv[t];
#pragma unroll 8
    for (int d = 0; d < D; d++) upd = fmaf(sU[d], wv[t * D + d], upd);
    sUpd[t] = upd;
    __syncthreads();
    float gi[3], gh[3];
#pragma unroll
    for (int k = 0; k < 3; k++) {
        int g = t + k * D;
        float ai = gbi[g], ah = gbh[g];
#pragma unroll 8
        for (int d = 0; d < D; d++) {
            ai = fmaf(sUpd[d], gwi[g * D + d], ai);
            ah = fmaf(sS[d], gwh[g * D + d], ah);
        }
        gi[k] = ai; gh[k] = ah;
    }
    float r = 1.0f / (1.0f + __expf(-(gi[0] + gh[0])));
    float z = 1.0f / (1.0f + __expf(-(gi[1] + gh[1])));
    float n = tanhf(gi[2] + r * gh[2]);
    float snew = (1.0f - z) * n + z * slot;
    // LayerNorm(snew)
    float mean = blockSum4(snew, red) * (1.0f / D);
    float d0 = snew - mean;
    float var = blockSum4(d0 * d0, red) * (1.0f / D);
    float rstd = rsqrtf(var + LN_EPS);
    float hln = d0 * rstd * lnw[t] + lnb[t];
    __syncthreads();
    sU[t] = hln;                    // reuse sU as hidden buffer
    __syncthreads();
#pragma unroll
    for (int k = 0; k < 4; k++) {
        int hh = t + k * D;
        float m = b1[hh];
#pragma unroll 8
        for (int d = 0; d < D; d++) m = fmaf(sU[d], w1[hh * D + d], m);
        sM[hh] = fmaxf(m, 0.f);
    }
    __syncthreads();
    float o = b2[t];
#pragma unroll 8
    for (int h = 0; h < H; h++) o = fmaf(sM[h], w2[t * H + h], o);
    o += snew;
    g_slots[row * D + t] = o;
    if (write_out) out[row * D + t] = o;
}

// ============================================================
extern "C" void kernel_launch(void* const* d_in, const int* in_sizes, int n_in,
                              void* d_out, int out_size) {
    (void)in_sizes; (void)n_in; (void)out_size;
    const float* queries = (const float*)d_in[0];
    const float* inputs  = (const float*)d_in[1];
    const float* wq  = (const float*)d_in[2];
    const float* bq  = (const float*)d_in[3];
    const float* wk  = (const float*)d_in[4];
    const float* bk  = (const float*)d_in[5];
    const float* wv  = (const float*)d_in[6];
    const float* bv  = (const float*)d_in[7];
    const float* gwi = (const float*)d_in[8];
    const float* gwh = (const float*)d_in[9];
    const float* gbi = (const float*)d_in[10];
    const float* gbh = (const float*)d_in[11];
    const float* w1  = (const float*)d_in[12];
    const float* b1  = (const float*)d_in[13];
    const float* w2  = (const float*)d_in[14];
    const float* b2  = (const float*)d_in[15];
    const float* ln_in_w = (const float*)d_in[16];
    const float* ln_in_b = (const float*)d_in[17];
    const float* ln_q_w  = (const float*)d_in[18];
    const float* ln_q_b  = (const float*)d_in[19];
    const float* ln_ff_w = (const float*)d_in[20];
    const float* ln_ff_b = (const float*)d_in[21];
    float* out = (float*)d_out;

    ln_in_kernel<<<B * NS / 8, 256>>>(inputs, ln_in_w, ln_in_b);
    init_slots_kernel<<<B * NQ * D / 256, 256>>>(queries);
    for (int it = 0; it < ITERS; it++) {
        pre_kernel<<<B * NQ, D>>>(wq, bq, wk, bk, ln_q_w, ln_q_b);
        attn_kernel<<<dim3(CHUNKS, B), 256>>>();
        post_kernel<<<B * NQ, D>>>(wv, bv, gwi, gwh, gbi, gbh,
                                   w1, b1, w2, b2, ln_ff_w, ln_ff_b,
                                   out, it == ITERS - 1 ? 1 : 0);
    }
}

// round 4
// speedup vs baseline: 1.7994x; 1.7994x over previous
#include <cuda_runtime.h>
#include <cuda_fp16.h>
#include <cstdint>

#define FULLMASK 0xFFFFFFFFu

namespace {
constexpr int   B       = 16;
constexpr int   NQ      = 8;
constexpr int   NS      = 16384;
constexpr int   D       = 128;
constexpr int   H       = 512;
constexpr int   ITERS   = 3;
constexpr float LN_EPS  = 1e-5f;
constexpr float EPS_A   = 1e-8f;
constexpr float SCALE   = 0.088388347648318447f;   // 128^-0.5
constexpr int   CHUNKS  = 64;                      // NS chunks per batch
constexpr int   RPC     = NS / CHUNKS;             // 256 rows per block
constexpr int   D2      = D / 2;                   // half2 elements per row
}

// ---- scratch (static __device__ arrays: allocation-free) ----
__device__ __half2 g_xn[(size_t)B * NS * D2];  // LayerNorm'd inputs, fp16, 67 MB
__device__ float g_slots[B * NQ * D];
__device__ float g_qk[B * NQ * D];             // SCALE * (q @ Wk)
__device__ float g_tt[B * NQ];                 // SCALE * (q . bk)
__device__ float g_U[B * NQ * D];              // sum_j a_ij * xn_j
__device__ float g_den[B * NQ];                // sum_j a_ij

// ============================================================
// Kernel 1: xn = fp16(LayerNorm(inputs)) — one warp per row
// ============================================================
__global__ void ln_in_kernel(const float* __restrict__ inp,
                             const float* __restrict__ w,
                             const float* __restrict__ b) {
    int warp = threadIdx.x >> 5, lane = threadIdx.x & 31;
    size_t row = (size_t)blockIdx.x * 8 + warp;
    const float4 x = *(const float4*)(inp + row * D + lane * 4);
    float s = x.x + x.y + x.z + x.w;
#pragma unroll
    for (int m = 16; m; m >>= 1) s += __shfl_xor_sync(FULLMASK, s, m);
    float mean = s * (1.0f / D);
    float dx = x.x - mean, dy = x.y - mean, dz = x.z - mean, dw = x.w - mean;
    float ss = dx * dx + dy * dy + dz * dz + dw * dw;
#pragma unroll
    for (int m = 16; m; m >>= 1) ss += __shfl_xor_sync(FULLMASK, ss, m);
    float rstd = rsqrtf(ss * (1.0f / D) + LN_EPS);
    const float4 wv = *(const float4*)(w + lane * 4);
    const float4 bv = *(const float4*)(b + lane * 4);
    float ox = dx * rstd * wv.x + bv.x;
    float oy = dy * rstd * wv.y + bv.y;
    float oz = dz * rstd * wv.z + bv.z;
    float ow = dw * rstd * wv.w + bv.w;
    __half2 h0 = __floats2half2_rn(ox, oy);
    __half2 h1 = __floats2half2_rn(oz, ow);
    uint2 packed;
    packed.x = *reinterpret_cast<uint32_t*>(&h0);
    packed.y = *reinterpret_cast<uint32_t*>(&h1);
    *(uint2*)(g_xn + row * D2 + lane * 2) = packed;
}

__global__ void init_slots_kernel(const float* __restrict__ q) {
    int i = blockIdx.x * blockDim.x + threadIdx.x;
    g_slots[i] = q[i];
}

// 512-thread block sum (16 warps); returns full-block sum to all threads
__device__ __forceinline__ float blockSum512(float v, float* red) {
#pragma unroll
    for (int m = 16; m; m >>= 1) v += __shfl_xor_sync(FULLMASK, v, m);
    __syncthreads();
    if ((threadIdx.x & 31) == 0) red[threadIdx.x >> 5] = v;
    __syncthreads();
    float s = 0.f;
#pragma unroll
    for (int i = 0; i < 16; i++) s += red[i];
    return s;
}

// quad reduce: sum across lanes 4k..4k+3 (thread = e*4+q)
__device__ __forceinline__ float quadSum(float v) {
    v += __shfl_xor_sync(FULLMASK, v, 1);
    v += __shfl_xor_sync(FULLMASK, v, 2);
    return v;
}

// 32-element quarter-dot with float4 loads, 4 independent chains
__device__ __forceinline__ float qdot(const float* __restrict__ vec,
                                      const float* __restrict__ mat_row, int q) {
    float a0 = 0.f, a1 = 0.f, a2 = 0.f, a3 = 0.f;
    const float4* m = (const float4*)(mat_row + q * 32);
    const float4* s = (const float4*)(vec + q * 32);
#pragma unroll
    for (int j = 0; j < 8; j++) {
        float4 mv = m[j];
        float4 sv = s[j];
        a0 = fmaf(sv.x, mv.x, a0);
        a1 = fmaf(sv.y, mv.y, a1);
        a2 = fmaf(sv.z, mv.z, a2);
        a3 = fmaf(sv.w, mv.w, a3);
    }
    return (a0 + a1) + (a2 + a3);
}

// ============================================================
// Kernel 2 (per iter): q = LN(slots)@Wq^T+bq ; qk = SCALE*(q@Wk)
// t = SCALE*(q.bk) ; zero U/den.  One 512-thr block per (b,i) row.
// thread = (e, q): e = tid>>2 in [0,128), q = tid&3 quarter role.
// ============================================================
__global__ void __launch_bounds__(512) pre_kernel(
        const float* __restrict__ wq, const float* __restrict__ bq,
        const float* __restrict__ wk, const float* __restrict__ bk,
        const float* __restrict__ lnw, const float* __restrict__ lnb) {
    int row = blockIdx.x;            // b*NQ + i
    int tid = threadIdx.x;
    int e = tid >> 2, q = tid & 3;
    __shared__ float sh[D], sq[D], red[16];
    float s = g_slots[row * D + e];                 // x4 redundant
    float mean = blockSum512(s, red) * (1.0f / (4 * D));
    float d0 = s - mean;
    float var = blockSum512(d0 * d0, red) * (1.0f / (4 * D));
    float rstd = rsqrtf(var + LN_EPS);
    if (q == 0) sh[e] = d0 * rstd * lnw[e] + lnb[e];
    __syncthreads();
    // q-projection: output e, quarter q
    float acc = quadSum(qdot(sh, wq + e * D, q));
    if (q == 0) sq[e] = acc + bq[e];
    __syncthreads();
    // qk[e] = SCALE * sum_d sq[d] * wk[d*D+e]  (column access)
    float qk = 0.f;
#pragma unroll 8
    for (int j = 0; j < 32; j++) {
        int d = q * 32 + j;
        qk = fmaf(sq[d], wk[d * D + e], qk);
    }
    qk = quadSum(qk);
    if (q == 0) g_qk[row * D + e] = qk * SCALE;
    // tb = SCALE * sum_e sq[e]*bk[e]
    float tv = (q == 0) ? sq[e] * bk[e] : 0.f;
    float tb = blockSum512(tv, red);
    if (tid == 0) { g_tt[row] = tb * SCALE; g_den[row] = 0.f; }
    if (q == 0) g_U[row * D + e] = 0.f;
}

// ============================================================
// Kernel 3 (per iter): fused attention streaming pass over xn.
// ============================================================
__global__ void __launch_bounds__(256, 2) attn_kernel() {
    int b = blockIdx.y;
    int cx = blockIdx.x;
    int tid = threadIdx.x;
    int warp = tid >> 5, lane = tid & 31;
    __shared__ __align__(16) float sqk[NQ * D];
    __shared__ float sUsh[NQ * D];
    __shared__ float st[NQ];
    __shared__ float sden[NQ];
    for (int i = tid; i < NQ * D; i += 256) {
        sqk[i] = g_qk[b * NQ * D + i];
        sUsh[i] = 0.f;
    }
    if (tid < NQ) { st[tid] = g_tt[b * NQ + tid]; sden[tid] = 0.f; }
    __syncthreads();

    float4 rq[NQ];
#pragma unroll
    for (int i = 0; i < NQ; i++) rq[i] = *(const float4*)(sqk + i * D + lane * 4);
    float tb = st[lane >> 2];        // this lane's query role rid = lane>>2

    float U[NQ][4];
#pragma unroll
    for (int i = 0; i < NQ; i++) { U[i][0] = 0.f; U[i][1] = 0.f; U[i][2] = 0.f; U[i][3] = 0.f; }
    float dacc = 0.f;

    const __half2* __restrict__ base =
        g_xn + ((size_t)b * NS + (size_t)cx * RPC + warp * 32) * D2 + lane * 2;

    uint2 raw = *(const uint2*)(base);           // prefetch row 0
#pragma unroll 4
    for (int r = 0; r < 32; r++) {
        uint2 rawc = raw;
        if (r < 31) raw = *(const uint2*)(base + (size_t)(r + 1) * D2);  // prefetch next
        __half2 h0 = *reinterpret_cast<__half2*>(&rawc.x);
        __half2 h1 = *reinterpret_cast<__half2*>(&rawc.y);
        float2 f0 = __half22float2(h0);
        float2 f1 = __half22float2(h1);
        float4 xc; xc.x = f0.x; xc.y = f0.y; xc.z = f1.x; xc.w = f1.y;

        float p[NQ];
#pragma unroll
        for (int i = 0; i < NQ; i++)
            p[i] = fmaf(rq[i].x, xc.x, fmaf(rq[i].y, xc.y, fmaf(rq[i].z, xc.z, rq[i].w * xc.w)));

        // --- value-halving reduction: 8 dots over 32 lanes ---
        float sm0[8];
#pragma unroll
        for (int i = 0; i < 8; i++) sm0[i] = p[i] + __shfl_xor_sync(FULLMASK, p[i], 16);
        bool h16 = (lane & 16) != 0;
        float q0 = h16 ? sm0[4] : sm0[0];
        float q1 = h16 ? sm0[5] : sm0[1];
        float q2 = h16 ? sm0[6] : sm0[2];
        float q3 = h16 ? sm0[7] : sm0[3];
        float t0 = q0 + __shfl_xor_sync(FULLMASK, q0, 8);
        float t1 = q1 + __shfl_xor_sync(FULLMASK, q1, 8);
        float t2 = q2 + __shfl_xor_sync(FULLMASK, q2, 8);
        float t3 = q3 + __shfl_xor_sync(FULLMASK, q3, 8);
        bool h8 = (lane & 8) != 0;
        float u0 = h8 ? t2 : t0;
        float u1 = h8 ? t3 : t1;
        float v0 = u0 + __shfl_xor_sync(FULLMASK, u0, 4);
        float v1 = u1 + __shfl_xor_sync(FULLMASK, u1, 4);
        float w0 = ((lane & 4) != 0) ? v1 : v0;
        w0 += __shfl_xor_sync(FULLMASK, w0, 2);
        w0 += __shfl_xor_sync(FULLMASK, w0, 1);
        // lane now holds full dot for query rid = lane>>2 (x4 redundancy)

        float e = __expf(w0 + tb);
        float ssum = e;
        ssum += __shfl_xor_sync(FULLMASK, ssum, 4);
        ssum += __shfl_xor_sync(FULLMASK, ssum, 8);
        ssum += __shfl_xor_sync(FULLMASK, ssum, 16);   // sum over the 8 roles
        float a_self = __fdividef(e, ssum) + EPS_A;
        dacc += a_self;
        float a[NQ];
#pragma unroll
        for (int i = 0; i < NQ; i++) a[i] = __shfl_sync(FULLMASK, a_self, i * 4);
#pragma unroll
        for (int i = 0; i < NQ; i++) {
            U[i][0] = fmaf(a[i], xc.x, U[i][0]);
            U[i][1] = fmaf(a[i], xc.y, U[i][1]);
            U[i][2] = fmaf(a[i], xc.z, U[i][2]);
            U[i][3] = fmaf(a[i], xc.w, U[i][3]);
        }
    }

    // block-level reduce via shared atomics, then one global pass
#pragma unroll
    for (int i = 0; i < NQ; i++) {
        atomicAdd(&sUsh[i * D + lane * 4 + 0], U[i][0]);
        atomicAdd(&sUsh[i * D + lane * 4 + 1], U[i][1]);
        atomicAdd(&sUsh[i * D + lane * 4 + 2], U[i][2]);
        atomicAdd(&sUsh[i * D + lane * 4 + 3], U[i][3]);
    }
    if ((lane & 3) == 0) atomicAdd(&sden[lane >> 2], dacc);
    __syncthreads();
    for (int i = tid; i < NQ * D; i += 256) atomicAdd(&g_U[b * NQ * D + i], sUsh[i]);
    if (tid < NQ) atomicAdd(&g_den[b * NQ + tid], sden[tid]);
}

// ============================================================
// Kernel 4 (per iter): updates = (U/den)@Wv^T+bv ; GRU ; slots+FF
// One 512-thread block per (b,i) row. thread = (e, q).
// ============================================================
__global__ void __launch_bounds__(512) post_kernel(
        const float* __restrict__ wv, const float* __restrict__ bv,
        const float* __restrict__ gwi, const float* __restrict__ gwh,
        const float* __restrict__ gbi, const float* __restrict__ gbh,
        const float* __restrict__ w1, const float* __restrict__ b1,
        const float* __restrict__ w2, const float* __restrict__ b2,
        const float* __restrict__ lnw, const float* __restrict__ lnb,
        float* __restrict__ out, int write_out) {
    int row = blockIdx.x;
    int tid = threadIdx.x;
    int e = tid >> 2, q = tid & 3;
    __shared__ float sU[D], sUpd[D], sS[D], sM[H], red[16];
    float den = g_den[row];
    float slot = g_slots[row * D + e];              // x4 redundant
    if (q == 0) {
        sU[e] = g_U[row * D + e] / den;
        sS[e] = slot;
    }
    __syncthreads();
    // updates = (U/den) @ Wv^T + bv
    float upd = quadSum(qdot(sU, wv + e * D, q));
    if (q == 0) sUpd[e] = upd + bv[e];
    __syncthreads();
    // GRU gates: for k=0..2, gate index g = e + k*D
    float gi[3], gh[3];
#pragma unroll
    for (int k = 0; k < 3; k++) {
        int g = e + k * D;
        float ai = quadSum(qdot(sUpd, gwi + g * D, q));
        float ah = quadSum(qdot(sS, gwh + g * D, q));
        gi[k] = ai + gbi[g];
        gh[k] = ah + gbh[g];
    }
    float r = 1.0f / (1.0f + __expf(-(gi[0] + gh[0])));
    float z = 1.0f / (1.0f + __expf(-(gi[1] + gh[1])));
    float n = tanhf(gi[2] + r * gh[2]);
    float snew = (1.0f - z) * n + z * slot;         // same in all 4 roles
    // LayerNorm(snew) over 128 elems (x4 redundancy)
    float mean = blockSum512(snew, red) * (1.0f / (4 * D));
    float d0 = snew - mean;
    float var = blockSum512(d0 * d0, red) * (1.0f / (4 * D));
    float rstd = rsqrtf(var + LN_EPS);
    if (q == 0) sU[e] = d0 * rstd * lnw[e] + lnb[e];   // reuse sU as hidden
    __syncthreads();
    // MLP layer 1: one output per thread (H = 512)
    {
        float a0 = 0.f, a1 = 0.f, a2 = 0.f, a3 = 0.f;
        const float4* m = (const float4*)(w1 + tid * D);
        const float4* s4 = (const float4*)(sU);
#pragma unroll
        for (int j = 0; j < 32; j++) {
            float4 mv = m[j];
            float4 sv = s4[j];
            a0 = fmaf(sv.x, mv.x, a0);
            a1 = fmaf(sv.y, mv.y, a1);
            a2 = fmaf(sv.z, mv.z, a2);
            a3 = fmaf(sv.w, mv.w, a3);
        }
        sM[tid] = fmaxf((a0 + a1) + (a2 + a3) + b1[tid], 0.f);
    }
    __syncthreads();
    // MLP layer 2: output e, quarter q over H=512 (128 each)
    {
        float a0 = 0.f, a1 = 0.f, a2 = 0.f, a3 = 0.f;
        const float4* m = (const float4*)(w2 + e * H + q * 128);
        const float4* s4 = (const float4*)(sM + q * 128);
#pragma unroll
        for (int j = 0; j < 32; j++) {
            float4 mv = m[j];
            float4 sv = s4[j];
            a0 = fmaf(sv.x, mv.x, a0);
            a1 = fmaf(sv.y, mv.y, a1);
            a2 = fmaf(sv.z, mv.z, a2);
            a3 = fmaf(sv.w, mv.w, a3);
        }
        float o = quadSum((a0 + a1) + (a2 + a3));
        if (q == 0) {
            o += b2[e] + snew;
            g_slots[row * D + e] = o;
            if (write_out) out[row * D + e] = o;
        }
    }
}

// ============================================================
extern "C" void kernel_launch(void* const* d_in, const int* in_sizes, int n_in,
                              void* d_out, int out_size) {
    (void)in_sizes; (void)n_in; (void)out_size;
    const float* queries = (const float*)d_in[0];
    const float* inputs  = (const float*)d_in[1];
    const float* wq  = (const float*)d_in[2];
    const float* bq  = (const float*)d_in[3];
    const float* wk  = (const float*)d_in[4];
    const float* bk  = (const float*)d_in[5];
    const float* wv  = (const float*)d_in[6];
    const float* bv  = (const float*)d_in[7];
    const float* gwi = (const float*)d_in[8];
    const float* gwh = (const float*)d_in[9];
    const float* gbi = (const float*)d_in[10];
    const float* gbh = (const float*)d_in[11];
    const float* w1  = (const float*)d_in[12];
    const float* b1  = (const float*)d_in[13];
    const float* w2  = (const float*)d_in[14];
    const float* b2  = (const float*)d_in[15];
    const float* ln_in_w = (const float*)d_in[16];
    const float* ln_in_b = (const float*)d_in[17];
    const float* ln_q_w  = (const float*)d_in[18];
    const float* ln_q_b  = (const float*)d_in[19];
    const float* ln_ff_w = (const float*)d_in[20];
    const float* ln_ff_b = (const float*)d_in[21];
    float* out = (float*)d_out;

    ln_in_kernel<<<B * NS / 8, 256>>>(inputs, ln_in_w, ln_in_b);
    init_slots_kernel<<<B * NQ * D / 256, 256>>>(queries);
    for (int it = 0; it < ITERS; it++) {
        pre_kernel<<<B * NQ, 512>>>(wq, bq, wk, bk, ln_q_w, ln_q_b);
        attn_kernel<<<dim3(CHUNKS, B), 256>>>();
        post_kernel<<<B * NQ, 512>>>(wv, bv, gwi, gwh, gbi, gbh,
                                     w1, b1, w2, b2, ln_ff_w, ln_ff_b,
                                     out, it == ITERS - 1 ? 1 : 0);
    }
}